// round 3
// baseline (speedup 1.0000x reference)
#include <cuda_runtime.h>
#include <stdint.h>

#define N_NODES 1000000
#define N_EDGES 10000000
#define HIDDEN  8
#define N_GRAPHS 64

// ---- scratch (device globals; no allocation allowed) ----
__device__ int   g_is64;                     // 1 if index inputs are int64
__device__ int   g_deg [N_NODES];
__device__ float g_dinv[N_NODES];
__device__ float g_g   [N_NODES * HIDDEN];   // per-node (h@W)*dinv
__device__ float g_agg [N_NODES * HIDDEN];   // scatter accumulator
__device__ int2  g_e32 [N_EDGES];            // packed (src,dst) int32

// ---- kernels ----

// Probe whether edge_index is int64 or int32. For int64 values < 2^31,
// every odd 32-bit word is 0. For uniform int32 in [0, 1M), odd words are
// ~never 0 (p=1e-6 each). Inspect 128 words.
__global__ void k_detect(const void* __restrict__ ei_raw) {
    const int* w = (const int*)ei_raw;
    int zeros = 0;
    for (int i = 1; i < 128; i += 2)
        if (w[i] == 0) zeros++;
    g_is64 = (zeros >= 48) ? 1 : 0;   // 64 odd words inspected
}

__global__ void k_init_deg() {
    int i = blockIdx.x * blockDim.x + threadIdx.x;
    if (i < N_NODES) g_deg[i] = 0;
}

// read edge_index [2, E] (int32 or int64); pack to int2; count in-degree of dst
__global__ void k_prep_edges(const void* __restrict__ ei_raw) {
    int e = blockIdx.x * blockDim.x + threadIdx.x;
    if (e < N_EDGES) {
        int s, d;
        if (g_is64) {
            const long long* p = (const long long*)ei_raw;
            s = (int)p[e];
            d = (int)p[N_EDGES + e];
        } else {
            const int* p = (const int*)ei_raw;
            s = p[e];
            d = p[N_EDGES + e];
        }
        g_e32[e] = make_int2(s, d);
        atomicAdd(&g_deg[d], 1);
    }
}

// layer-1 transform: dinv, g = x*W1*dinv, agg = 0
__global__ void k_transform1(const float* __restrict__ x,
                             const float* __restrict__ W1) {
    __shared__ float sW[HIDDEN];
    if (threadIdx.x < HIDDEN) sW[threadIdx.x] = W1[threadIdx.x];
    __syncthreads();
    int i = blockIdx.x * blockDim.x + threadIdx.x;
    if (i < N_NODES) {
        float dinv = rsqrtf((float)g_deg[i] + 1.0f);
        g_dinv[i] = dinv;
        float xv = x[i] * dinv;
        float4 a = make_float4(xv * sW[0], xv * sW[1], xv * sW[2], xv * sW[3]);
        float4 b = make_float4(xv * sW[4], xv * sW[5], xv * sW[6], xv * sW[7]);
        float4* gp = (float4*)(g_g + (size_t)i * HIDDEN);
        gp[0] = a; gp[1] = b;
        float4 z = make_float4(0.f, 0.f, 0.f, 0.f);
        float4* ap = (float4*)(g_agg + (size_t)i * HIDDEN);
        ap[0] = z; ap[1] = z;
    }
}

// edge pass: agg[dst] += g[src]   (scalar reductions; ptxas emits REDG)
__global__ void k_edge_pass() {
    int e = blockIdx.x * blockDim.x + threadIdx.x;
    if (e < N_EDGES) {
        int2 sd = g_e32[e];
        const float4* gs = (const float4*)(g_g + (size_t)sd.x * HIDDEN);
        float4 a = gs[0];
        float4 b = gs[1];
        float* addr = g_agg + (size_t)sd.y * HIDDEN;
        atomicAdd(addr + 0, a.x);
        atomicAdd(addr + 1, a.y);
        atomicAdd(addr + 2, a.z);
        atomicAdd(addr + 3, a.w);
        atomicAdd(addr + 4, b.x);
        atomicAdd(addr + 5, b.y);
        atomicAdd(addr + 6, b.z);
        atomicAdd(addr + 7, b.w);
    }
}

// mid transform: finalize prev layer (+b_prev, relu), matmul W, rescale, reset agg
__global__ void k_transform_mid(const float* __restrict__ W,
                                const float* __restrict__ b_prev) {
    __shared__ float sW[HIDDEN * HIDDEN];
    __shared__ float sB[HIDDEN];
    if (threadIdx.x < HIDDEN * HIDDEN) sW[threadIdx.x] = W[threadIdx.x];
    if (threadIdx.x < HIDDEN) sB[threadIdx.x] = b_prev[threadIdx.x];
    __syncthreads();
    int i = blockIdx.x * blockDim.x + threadIdx.x;
    if (i < N_NODES) {
        float dinv = g_dinv[i];
        float4* ap = (float4*)(g_agg + (size_t)i * HIDDEN);
        float4* gp = (float4*)(g_g + (size_t)i * HIDDEN);
        float4 a0 = ap[0], a1 = ap[1];
        float4 g0 = gp[0], g1 = gp[1];
        float h[HIDDEN];
        h[0] = fmaxf(dinv * (a0.x + g0.x) + sB[0], 0.f);
        h[1] = fmaxf(dinv * (a0.y + g0.y) + sB[1], 0.f);
        h[2] = fmaxf(dinv * (a0.z + g0.z) + sB[2], 0.f);
        h[3] = fmaxf(dinv * (a0.w + g0.w) + sB[3], 0.f);
        h[4] = fmaxf(dinv * (a1.x + g1.x) + sB[4], 0.f);
        h[5] = fmaxf(dinv * (a1.y + g1.y) + sB[5], 0.f);
        h[6] = fmaxf(dinv * (a1.z + g1.z) + sB[6], 0.f);
        h[7] = fmaxf(dinv * (a1.w + g1.w) + sB[7], 0.f);
        float o[HIDDEN];
        #pragma unroll
        for (int j = 0; j < HIDDEN; j++) {
            float acc = 0.f;
            #pragma unroll
            for (int k = 0; k < HIDDEN; k++)
                acc = fmaf(h[k], sW[k * HIDDEN + j], acc);
            o[j] = acc * dinv;
        }
        gp[0] = make_float4(o[0], o[1], o[2], o[3]);
        gp[1] = make_float4(o[4], o[5], o[6], o[7]);
        float4 z = make_float4(0.f, 0.f, 0.f, 0.f);
        ap[0] = z; ap[1] = z;
    }
}

// final gather: out[k] = dinv[n]*(agg[n]+g[n]) + b4
__global__ void k_gather(const void* __restrict__ indices_raw,
                         const float* __restrict__ b4,
                         float* __restrict__ out) {
    int k = blockIdx.x * blockDim.x + threadIdx.x;
    if (k < N_GRAPHS) {
        int n;
        if (g_is64) n = (int)((const long long*)indices_raw)[k];
        else        n = ((const int*)indices_raw)[k];
        float dinv = g_dinv[n];
        #pragma unroll
        for (int j = 0; j < HIDDEN; j++)
            out[k * HIDDEN + j] =
                dinv * (g_agg[(size_t)n * HIDDEN + j] + g_g[(size_t)n * HIDDEN + j]) + b4[j];
    }
}

extern "C" void kernel_launch(void* const* d_in, const int* in_sizes, int n_in,
                              void* d_out, int out_size) {
    const float* x   = (const float*)d_in[0];
    const void*  ei  = d_in[1];
    const void*  idx = d_in[2];
    const float* W1 = (const float*)d_in[3];
    const float* b1 = (const float*)d_in[4];
    const float* W2 = (const float*)d_in[5];
    const float* b2 = (const float*)d_in[6];
    const float* W3 = (const float*)d_in[7];
    const float* b3 = (const float*)d_in[8];
    const float* W4 = (const float*)d_in[9];
    const float* b4 = (const float*)d_in[10];
    float* out = (float*)d_out;

    const int TB = 256;
    int nb_nodes = (N_NODES + TB - 1) / TB;
    int nb_edges = (N_EDGES + TB - 1) / TB;

    k_detect<<<1, 1>>>(ei);
    k_init_deg<<<nb_nodes, TB>>>();
    k_prep_edges<<<nb_edges, TB>>>(ei);
    k_transform1<<<nb_nodes, TB>>>(x, W1);
    k_edge_pass<<<nb_edges, TB>>>();
    k_transform_mid<<<nb_nodes, TB>>>(W2, b1);
    k_edge_pass<<<nb_edges, TB>>>();
    k_transform_mid<<<nb_nodes, TB>>>(W3, b2);
    k_edge_pass<<<nb_edges, TB>>>();
    k_transform_mid<<<nb_nodes, TB>>>(W4, b3);
    k_edge_pass<<<nb_edges, TB>>>();
    k_gather<<<1, 64>>>(idx, b4, out);
}

// round 4
// speedup vs baseline: 2.7242x; 2.7242x over previous
#include <cuda_runtime.h>
#include <stdint.h>

#define NN 1000000
#define NE 10000000
#define HID 8
#define NG 64
#define NW 31250          // bitmap words (1M / 32)

#define CAP1 2097152
#define CAP2 409600
#define CAP3 65536
#define CAP4 16384

// ---- device scratch (statics; no allocation) ----
__device__ int      g_is64;
__device__ int      g_deg[NN];
__device__ float    g_dinv[NN];
__device__ float    g_v1[NN * HID];      // g1, later g3
__device__ float    g_v2[NN * HID];      // g2, later g4
__device__ float    g_agg[NN * HID];
__device__ int2     g_e32[NE];
__device__ unsigned g_bm_idx[NW], g_bm4[NW], g_bm3[NW], g_bm2[NW];
__device__ int2     g_el1[CAP1], g_el2[CAP2], g_el3[CAP3], g_el4[CAP4];
__device__ int      g_cnt1, g_cnt2, g_cnt3, g_cnt4;

__device__ __forceinline__ bool bm_test(const unsigned* bm, int i) {
    return (bm[i >> 5] >> (i & 31)) & 1u;
}
__device__ __forceinline__ void bm_set(unsigned* bm, int i) {
    atomicOr(&bm[i >> 5], 1u << (i & 31));
}

// dtype probe: int64 values < 2^31 have all odd 32-bit words == 0
__global__ void k_detect(const void* __restrict__ ei_raw) {
    const int* w = (const int*)ei_raw;
    int zeros = 0;
    for (int i = 1; i < 128; i += 2)
        if (w[i] == 0) zeros++;
    g_is64 = (zeros >= 48) ? 1 : 0;
}

// zero deg, bitmaps, counters (grid-stride)
__global__ void k_init() {
    int i = blockIdx.x * blockDim.x + threadIdx.x;
    int stride = gridDim.x * blockDim.x;
    for (int k = i; k < NN; k += stride) g_deg[k] = 0;
    for (int k = i; k < NW; k += stride) {
        g_bm_idx[k] = 0; g_bm4[k] = 0; g_bm3[k] = 0; g_bm2[k] = 0;
    }
    if (i == 0) { g_cnt1 = 0; g_cnt2 = 0; g_cnt3 = 0; g_cnt4 = 0; }
}

__global__ void k_mark_idx(const void* __restrict__ idx_raw) {
    int k = threadIdx.x;
    if (k < NG) {
        int n = g_is64 ? (int)((const long long*)idx_raw)[k]
                       : ((const int*)idx_raw)[k];
        bm_set(g_bm_idx, n);
    }
}

// fused: pack int2, degree histogram, expand indices->S4 (capture EL4)
__global__ void k_pack(const void* __restrict__ ei_raw) {
    int e = blockIdx.x * blockDim.x + threadIdx.x;
    if (e >= NE) return;
    int s, d;
    if (g_is64) {
        const long long* p = (const long long*)ei_raw;
        s = (int)p[e]; d = (int)p[NE + e];
    } else {
        const int* p = (const int*)ei_raw;
        s = p[e]; d = p[NE + e];
    }
    g_e32[e] = make_int2(s, d);
    atomicAdd(&g_deg[d], 1);
    if (bm_test(g_bm_idx, d)) {
        bm_set(g_bm4, s);
        int p4 = atomicAdd(&g_cnt4, 1);
        if (p4 < CAP4) g_el4[p4] = make_int2(s, d);
    }
}

// stage 0: bm4 |= bm_idx ; 1: bm3 |= bm4 ; 2: bm2 |= bm3
__global__ void k_or(int stage) {
    int i = blockIdx.x * blockDim.x + threadIdx.x;
    if (i >= NW) return;
    if (stage == 0)      g_bm4[i] |= g_bm_idx[i];
    else if (stage == 1) g_bm3[i] |= g_bm4[i];
    else                 g_bm2[i] |= g_bm3[i];
}

__global__ void k_dinv() {
    int i = blockIdx.x * blockDim.x + threadIdx.x;
    if (i < NN) g_dinv[i] = rsqrtf((float)g_deg[i] + 1.0f);
}

// g1 = x * dinv * W1 (pointwise) for all nodes; zero agg
__global__ void k_g1(const float* __restrict__ x, const float* __restrict__ W1) {
    __shared__ float sW[HID];
    if (threadIdx.x < HID) sW[threadIdx.x] = W1[threadIdx.x];
    __syncthreads();
    int i = blockIdx.x * blockDim.x + threadIdx.x;
    if (i < NN) {
        float xv = x[i] * g_dinv[i];
        float4* gp = (float4*)(g_v1 + (size_t)i * HID);
        gp[0] = make_float4(xv * sW[0], xv * sW[1], xv * sW[2], xv * sW[3]);
        gp[1] = make_float4(xv * sW[4], xv * sW[5], xv * sW[6], xv * sW[7]);
        float4 z = make_float4(0.f, 0.f, 0.f, 0.f);
        float4* ap = (float4*)(g_agg + (size_t)i * HID);
        ap[0] = z; ap[1] = z;
    }
}

// expansion scans: stage 1: dst in bm4 -> mark bm3, EL3
//                  stage 2: dst in bm3 -> mark bm2, EL2
//                  stage 3: dst in bm2 -> EL1 (no marking)
__global__ void k_expand(int stage) {
    int e = blockIdx.x * blockDim.x + threadIdx.x;
    if (e >= NE) return;
    int2 sd = g_e32[e];
    if (stage == 1) {
        if (bm_test(g_bm4, sd.y)) {
            bm_set(g_bm3, sd.x);
            int p = atomicAdd(&g_cnt3, 1);
            if (p < CAP3) g_el3[p] = sd;
        }
    } else if (stage == 2) {
        if (bm_test(g_bm3, sd.y)) {
            bm_set(g_bm2, sd.x);
            int p = atomicAdd(&g_cnt2, 1);
            if (p < CAP2) g_el2[p] = sd;
        }
    } else {
        if (bm_test(g_bm2, sd.y)) {
            int p = atomicAdd(&g_cnt1, 1);
            if (p < CAP1) g_el1[p] = sd;
        }
    }
}

// sparse aggregation over a captured edge list: agg[dst] += gsrc[src]
__global__ void k_agg(int list_id, int src_sel) {
    int e = blockIdx.x * blockDim.x + threadIdx.x;
    int n; const int2* el;
    if (list_id == 1)      { n = min(g_cnt1, CAP1); el = g_el1; }
    else if (list_id == 2) { n = min(g_cnt2, CAP2); el = g_el2; }
    else if (list_id == 3) { n = min(g_cnt3, CAP3); el = g_el3; }
    else                   { n = min(g_cnt4, CAP4); el = g_el4; }
    if (e >= n) return;
    int2 sd = el[e];
    const float* gs = (src_sel ? g_v2 : g_v1) + (size_t)sd.x * HID;
    float4 a = ((const float4*)gs)[0];
    float4 b = ((const float4*)gs)[1];
    float* ad = g_agg + (size_t)sd.y * HID;
    atomicAdd(ad + 0, a.x); atomicAdd(ad + 1, a.y);
    atomicAdd(ad + 2, a.z); atomicAdd(ad + 3, a.w);
    atomicAdd(ad + 4, b.x); atomicAdd(ad + 5, b.y);
    atomicAdd(ad + 6, b.z); atomicAdd(ad + 7, b.w);
}

// sparse transform at bitmap nodes: h = relu(dinv*(agg+gin)+b_prev);
// gout = (h@W)*dinv ; agg reset
__global__ void k_transform(int bm_sel, int in_sel,
                            const float* __restrict__ W,
                            const float* __restrict__ b_prev) {
    __shared__ float sW[HID * HID];
    __shared__ float sB[HID];
    if (threadIdx.x < HID * HID) sW[threadIdx.x] = W[threadIdx.x];
    if (threadIdx.x < HID) sB[threadIdx.x] = b_prev[threadIdx.x];
    __syncthreads();
    int i = blockIdx.x * blockDim.x + threadIdx.x;
    if (i >= NN) return;
    const unsigned* bm = (bm_sel == 2) ? g_bm2 : (bm_sel == 3) ? g_bm3 : g_bm4;
    if (!bm_test(bm, i)) return;
    float dinv = g_dinv[i];
    float* gin  = (in_sel ? g_v2 : g_v1) + (size_t)i * HID;
    float* gout = (in_sel ? g_v1 : g_v2) + (size_t)i * HID;
    float* ag   = g_agg + (size_t)i * HID;
    float h[HID];
    #pragma unroll
    for (int j = 0; j < HID; j++) {
        h[j] = fmaxf(dinv * (ag[j] + gin[j]) + sB[j], 0.f);
        ag[j] = 0.f;
    }
    #pragma unroll
    for (int j = 0; j < HID; j++) {
        float acc = 0.f;
        #pragma unroll
        for (int k = 0; k < HID; k++)
            acc = fmaf(h[k], sW[k * HID + j], acc);
        gout[j] = acc * dinv;
    }
}

// final: out[k] = dinv*(agg + g4) + b4  (no relu), g4 lives in g_v2
__global__ void k_final(const void* __restrict__ idx_raw,
                        const float* __restrict__ b4,
                        float* __restrict__ out) {
    int k = threadIdx.x;
    if (k < NG) {
        int n = g_is64 ? (int)((const long long*)idx_raw)[k]
                       : ((const int*)idx_raw)[k];
        float dinv = g_dinv[n];
        #pragma unroll
        for (int j = 0; j < HID; j++)
            out[k * HID + j] =
                dinv * (g_agg[(size_t)n * HID + j] + g_v2[(size_t)n * HID + j]) + b4[j];
    }
}

extern "C" void kernel_launch(void* const* d_in, const int* in_sizes, int n_in,
                              void* d_out, int out_size) {
    const float* x  = (const float*)d_in[0];
    const void*  ei = d_in[1];
    const void*  idx = d_in[2];
    const float* W1 = (const float*)d_in[3];
    const float* b1 = (const float*)d_in[4];
    const float* W2 = (const float*)d_in[5];
    const float* b2 = (const float*)d_in[6];
    const float* W3 = (const float*)d_in[7];
    const float* b3 = (const float*)d_in[8];
    const float* W4 = (const float*)d_in[9];
    const float* b4 = (const float*)d_in[10];
    float* out = (float*)d_out;

    const int TB = 256;
    int nbN = (NN + TB - 1) / TB;
    int nbE = (NE + TB - 1) / TB;
    int nbW = (NW + TB - 1) / TB;

    k_detect<<<1, 1>>>(ei);
    k_init<<<1024, TB>>>();
    k_mark_idx<<<1, 64>>>(idx);
    k_pack<<<nbE, TB>>>(ei);               // pack + deg + EL4 + mark S4 srcs
    k_or<<<nbW, TB>>>(0);                  // bm4 |= bm_idx
    k_dinv<<<nbN, TB>>>();
    k_g1<<<nbN, TB>>>(x, W1);              // g1 everywhere, agg = 0
    k_expand<<<nbE, TB>>>(1);              // S4 -> S3, EL3
    k_or<<<nbW, TB>>>(1);                  // bm3 |= bm4
    k_expand<<<nbE, TB>>>(2);              // S3 -> S2, EL2
    k_or<<<nbW, TB>>>(2);                  // bm2 |= bm3
    k_expand<<<nbE, TB>>>(3);              // dst in S2 -> EL1
    k_agg<<<CAP1 / TB, TB>>>(1, 0);        // agg1 at S2 from g1(v1)
    k_transform<<<nbN, TB>>>(2, 0, W2, b1);// S2: g2 -> v2
    k_agg<<<CAP2 / TB, TB>>>(2, 1);        // agg2 at S3 from g2(v2)
    k_transform<<<nbN, TB>>>(3, 1, W3, b2);// S3: g3 -> v1
    k_agg<<<CAP3 / TB, TB>>>(3, 0);        // agg3 at S4 from g3(v1)
    k_transform<<<nbN, TB>>>(4, 0, W4, b3);// S4: g4 -> v2
    k_agg<<<CAP4 / TB, TB>>>(4, 1);        // agg4 at indices from g4(v2)
    k_final<<<1, 64>>>(idx, b4, out);
}

// round 6
// speedup vs baseline: 4.8640x; 1.7855x over previous
#include <cuda_runtime.h>
#include <stdint.h>

#define NN 1000000
#define NE 10000000
#define HID 8
#define NG 64
#define NW 31250

#define SCAN_B  1024
#define SCAN_NB 977          // ceil(NN / SCAN_B)

#define CAP2 262144
#define CAP3 32768
#define CAP4 8192

// ---- device scratch ----
__device__ int      g_is64;
__device__ int      g_deg[NN];
__device__ int      g_off[NN];
__device__ int      g_cur[NN];
__device__ float    g_dinv[NN];
__device__ int      g_csr[NE];           // src ids grouped by dst
__device__ int      g_bsum[SCAN_NB + 64], g_bscan[SCAN_NB + 64];
__device__ float    g_v1[NN * HID];      // g3
__device__ float    g_v2[NN * HID];      // g2, then g4
__device__ unsigned g_bm4[NW], g_bm3[NW], g_bm2[NW];
__device__ int      g_l2[CAP2], g_l3[CAP3], g_l4[CAP4];
__device__ int      g_c2, g_c3, g_c4;

__device__ __forceinline__ bool bm_claim(unsigned* bm, int i) {
    unsigned old = atomicOr(&bm[i >> 5], 1u << (i & 31));
    return !((old >> (i & 31)) & 1u);
}

// dtype probe: int64 values < 2^31 -> odd 32-bit words are 0
__global__ void k_detect(const void* __restrict__ ei_raw) {
    const int* w = (const int*)ei_raw;
    int zeros = 0;
    for (int i = 1; i < 128; i += 2)
        if (w[i] == 0) zeros++;
    g_is64 = (zeros >= 48) ? 1 : 0;
}

__global__ void k_init() {
    int i = blockIdx.x * blockDim.x + threadIdx.x;
    int stride = gridDim.x * blockDim.x;
    for (int k = i; k < NN; k += stride) g_deg[k] = 0;
    for (int k = i; k < NW; k += stride) { g_bm4[k] = 0; g_bm3[k] = 0; g_bm2[k] = 0; }
    if (i == 0) { g_c2 = 0; g_c3 = 0; g_c4 = 0; }
}

// degree histogram: read dst half only
__global__ void k_deg_k(const void* __restrict__ ei_raw) {
    int e = blockIdx.x * blockDim.x + threadIdx.x;
    if (e >= NE) return;
    int d = g_is64 ? (int)((const long long*)ei_raw)[NE + e]
                   : ((const int*)ei_raw)[NE + e];
    atomicAdd(&g_deg[d], 1);
}

// scan stage 1: per-block sums
__global__ void k_s1() {
    __shared__ int sh[SCAN_B];
    int i = blockIdx.x * SCAN_B + threadIdx.x;
    sh[threadIdx.x] = (i < NN) ? g_deg[i] : 0;
    __syncthreads();
    for (int s = SCAN_B / 2; s > 0; s >>= 1) {
        if (threadIdx.x < s) sh[threadIdx.x] += sh[threadIdx.x + s];
        __syncthreads();
    }
    if (threadIdx.x == 0) g_bsum[blockIdx.x] = sh[0];
}

// scan stage 2: exclusive scan of block sums (single block)
__global__ void k_s2() {
    __shared__ int sh[SCAN_B];
    int t = threadIdx.x;
    int v = (t < SCAN_NB) ? g_bsum[t] : 0;
    sh[t] = v;
    __syncthreads();
    for (int off = 1; off < SCAN_B; off <<= 1) {
        int u = (t >= off) ? sh[t - off] : 0;
        __syncthreads();
        sh[t] += u;
        __syncthreads();
    }
    if (t < SCAN_NB) g_bscan[t] = sh[t] - v;
}

// scan stage 3: per-block exclusive scan + offsets + cursors + dinv
__global__ void k_s3() {
    __shared__ int sh[SCAN_B];
    int i = blockIdx.x * SCAN_B + threadIdx.x;
    int t = threadIdx.x;
    int v = (i < NN) ? g_deg[i] : 0;
    sh[t] = v;
    __syncthreads();
    for (int off = 1; off < SCAN_B; off <<= 1) {
        int u = (t >= off) ? sh[t - off] : 0;
        __syncthreads();
        sh[t] += u;
        __syncthreads();
    }
    if (i < NN) {
        int o = g_bscan[blockIdx.x] + sh[t] - v;
        g_off[i] = o;
        g_cur[i] = o;
        g_dinv[i] = rsqrtf((float)v + 1.0f);
    }
}

// CSR scatter: csr[pos(dst)] = src
__global__ void k_scatter(const void* __restrict__ ei_raw) {
    int e = blockIdx.x * blockDim.x + threadIdx.x;
    if (e >= NE) return;
    int s, d;
    if (g_is64) {
        const long long* p = (const long long*)ei_raw;
        s = (int)p[e]; d = (int)p[NE + e];
    } else {
        const int* p = (const int*)ei_raw;
        s = p[e]; d = p[NE + e];
    }
    int pos = atomicAdd(&g_cur[d], 1);
    g_csr[pos] = s;
}

// stage 0 expansion: indices -> S4 = idx U N(idx)  (claim d and its in-nbrs)
__global__ void k_expand0(const void* __restrict__ idx_raw) {
    int k = threadIdx.x;
    if (k >= NG) return;
    int d = g_is64 ? (int)((const long long*)idx_raw)[k]
                   : ((const int*)idx_raw)[k];
    if (bm_claim(g_bm4, d)) {
        int p = atomicAdd(&g_c4, 1);
        if (p < CAP4) g_l4[p] = d;
    }
    int o = g_off[d], e = o + g_deg[d];
    for (; o < e; o++) {
        int s = g_csr[o];
        if (bm_claim(g_bm4, s)) {
            int p = atomicAdd(&g_c4, 1);
            if (p < CAP4) g_l4[p] = s;
        }
    }
}

// frontier expand via CSR rows. stage 1: l4 -> bm3/l3 ; stage 2: l3 -> bm2/l2
__global__ void k_expand(int stage) {
    int i = blockIdx.x * blockDim.x + threadIdx.x;
    int n_in = (stage == 1) ? min(g_c4, CAP4) : min(g_c3, CAP3);
    if (i >= n_in) return;
    int d = (stage == 1) ? g_l4[i] : g_l3[i];
    unsigned* bm_out = (stage == 1) ? g_bm3 : g_bm2;
    int* list_out    = (stage == 1) ? g_l3 : g_l2;
    int* cnt_out     = (stage == 1) ? &g_c3 : &g_c2;
    int cap          = (stage == 1) ? CAP3 : CAP2;
    if (bm_claim(bm_out, d)) {
        int p = atomicAdd(cnt_out, 1);
        if (p < cap) list_out[p] = d;
    }
    int o = g_off[d], e = o + g_deg[d];
    for (; o < e; o++) {
        int s = g_csr[o];
        if (bm_claim(bm_out, s)) {
            int p = atomicAdd(cnt_out, 1);
            if (p < cap) list_out[p] = s;
        }
    }
}

// layer 1+2 fused at S2 nodes (layer-1 agg is a scalar reduction):
// g2[d] = (relu(dinv_d*(sum_{src} x*dinv + x_d*dinv_d)*W1 + b1) @ W2) * dinv_d
__global__ void k_layer2(const float* __restrict__ x,
                         const float* __restrict__ W1,
                         const float* __restrict__ b1,
                         const float* __restrict__ W2) {
    int i = blockIdx.x * blockDim.x + threadIdx.x;
    if (i >= min(g_c2, CAP2)) return;
    int d = g_l2[i];
    float s = x[d] * g_dinv[d];
    int o = g_off[d], e = o + g_deg[d];
    for (; o < e; o++) {
        int src = g_csr[o];
        s += x[src] * g_dinv[src];
    }
    float dinv = g_dinv[d];
    float pre = dinv * s;
    float h[HID];
    #pragma unroll
    for (int j = 0; j < HID; j++)
        h[j] = fmaxf(pre * __ldg(&W1[j]) + __ldg(&b1[j]), 0.f);
    float* g2 = g_v2 + (size_t)d * HID;
    #pragma unroll
    for (int j = 0; j < HID; j++) {
        float acc = 0.f;
        #pragma unroll
        for (int k = 0; k < HID; k++)
            acc = fmaf(h[k], __ldg(&W2[k * HID + j]), acc);
        g2[j] = acc * dinv;
    }
}

// generic GCN layer over node list: gout[d] = (relu(dinv*(sum gin[src]+gin[d])+b)@W)*dinv
// stage 3: list3, gin=v2, gout=v1, W3/b2 ; stage 4: list4, gin=v1, gout=v2, W4/b3
__global__ void k_layer(int stage,
                        const float* __restrict__ W,
                        const float* __restrict__ b) {
    int i = blockIdx.x * blockDim.x + threadIdx.x;
    int n = (stage == 3) ? min(g_c3, CAP3) : min(g_c4, CAP4);
    if (i >= n) return;
    int d = (stage == 3) ? g_l3[i] : g_l4[i];
    const float* gin = (stage == 3) ? g_v2 : g_v1;
    float* gout      = (stage == 3) ? g_v1 : g_v2;
    float acc8[HID];
    const float* gd = gin + (size_t)d * HID;
    #pragma unroll
    for (int j = 0; j < HID; j++) acc8[j] = gd[j];
    int o = g_off[d], e = o + g_deg[d];
    for (; o < e; o++) {
        const float* gs = gin + (size_t)g_csr[o] * HID;
        #pragma unroll
        for (int j = 0; j < HID; j++) acc8[j] += gs[j];
    }
    float dinv = g_dinv[d];
    float h[HID];
    #pragma unroll
    for (int j = 0; j < HID; j++)
        h[j] = fmaxf(dinv * acc8[j] + __ldg(&b[j]), 0.f);
    float* go = gout + (size_t)d * HID;
    #pragma unroll
    for (int j = 0; j < HID; j++) {
        float a = 0.f;
        #pragma unroll
        for (int k = 0; k < HID; k++)
            a = fmaf(h[k], __ldg(&W[k * HID + j]), a);
        go[j] = a * dinv;
    }
}

// final: out[k] = dinv*(sum g4[src] + g4[d]) + b4 (g4 in v2, valid on S4)
__global__ void k_final(const void* __restrict__ idx_raw,
                        const float* __restrict__ b4,
                        float* __restrict__ out) {
    int k = threadIdx.x;
    if (k >= NG) return;
    int d = g_is64 ? (int)((const long long*)idx_raw)[k]
                   : ((const int*)idx_raw)[k];
    float acc8[HID];
    const float* gd = g_v2 + (size_t)d * HID;
    #pragma unroll
    for (int j = 0; j < HID; j++) acc8[j] = gd[j];
    int o = g_off[d], e = o + g_deg[d];
    for (; o < e; o++) {
        const float* gs = g_v2 + (size_t)g_csr[o] * HID;
        #pragma unroll
        for (int j = 0; j < HID; j++) acc8[j] += gs[j];
    }
    float dinv = g_dinv[d];
    #pragma unroll
    for (int j = 0; j < HID; j++)
        out[k * HID + j] = dinv * acc8[j] + __ldg(&b4[j]);
}

extern "C" void kernel_launch(void* const* d_in, const int* in_sizes, int n_in,
                              void* d_out, int out_size) {
    const float* x  = (const float*)d_in[0];
    const void*  ei = d_in[1];
    const void*  idx = d_in[2];
    const float* W1 = (const float*)d_in[3];
    const float* b1 = (const float*)d_in[4];
    const float* W2 = (const float*)d_in[5];
    const float* b2 = (const float*)d_in[6];
    const float* W3 = (const float*)d_in[7];
    const float* b3 = (const float*)d_in[8];
    const float* W4 = (const float*)d_in[9];
    const float* b4 = (const float*)d_in[10];
    float* out = (float*)d_out;

    const int TB = 256;
    int nbE = (NE + TB - 1) / TB;

    k_detect<<<1, 1>>>(ei);
    k_init<<<1024, TB>>>();
    k_deg_k<<<nbE, TB>>>(ei);
    k_s1<<<SCAN_NB, SCAN_B>>>();
    k_s2<<<1, SCAN_B>>>();
    k_s3<<<SCAN_NB, SCAN_B>>>();
    k_scatter<<<nbE, TB>>>(ei);
    k_expand0<<<1, 64>>>(idx);                   // idx -> S4
    k_expand<<<CAP4 / TB, TB>>>(1);              // S4 -> S3
    k_expand<<<CAP3 / TB, TB>>>(2);              // S3 -> S2
    k_layer2<<<CAP2 / TB, TB>>>(x, W1, b1, W2);  // g2 at S2 (v2)
    k_layer<<<CAP3 / TB, TB>>>(3, W3, b2);       // g3 at S3 (v1)
    k_layer<<<CAP4 / TB, TB>>>(4, W4, b3);       // g4 at S4 (v2)
    k_final<<<1, 64>>>(idx, b4, out);
}